// round 12
// baseline (speedup 1.0000x reference)
#include <cuda_runtime.h>
#include <cstddef>
#include <cstdint>

// VarConvND: 4096 independent GEMMs [B=64 x K=288] x [K=288 x C_OUT=16].
// tf32 MMA. 256-thread blocks: 8 warps = 4 m-tiles x 2 K-halves.
// K double-buffered (4 chunks x 72 rows) via cp.async.
//   out[b,c,s] = sum_k u[b,k]*w[k,c] + bias[s]*sum_k w[k,c]

#define S_TOT 4096
#define KK    288
#define CO    16
#define CI    32
#define BB    64
#define HH    64
#define WW    64
#define P_TOT (CI*HH*WW)            // 131072

#define AST   72                    // X row stride (words): A-frag reads hit 32 banks
#define WST   24                    // W row stride (words): B-frag reads hit 32 banks
#define CKR   72                    // k-rows per chunk
#define NCH   4                     // chunks

#define W_WORDS   (KK*WST)          // 6912
#define XB_WORDS  (CKR*AST)         // 5184
#define XB0_OFF   W_WORDS
#define XB1_OFF   (W_WORDS + XB_WORDS)
#define PAD_OFF   (W_WORDS + 2*XB_WORDS)
#define PAD_WORDS (4*32*8)          // 1024 (kh=1 acc dump)
#define CSUM_OFF  (PAD_OFF + PAD_WORDS)
#define SMEM_WORDS (CSUM_OFF + 32)
#define SMEM_BYTES (SMEM_WORDS * 4)   // 73,472

__device__ float g_Xt[(size_t)P_TOT * BB];        // X^T, tf32-rounded, [p][b]
__device__ float g_Os[(size_t)S_TOT * BB * CO];   // out scratch [s][b*16+c]

__device__ __forceinline__ unsigned f2tf(float f)
{
    unsigned u;
    asm("cvt.rna.tf32.f32 %0, %1;" : "=r"(u) : "f"(f));
    return u;
}

// ---------- transpose + tf32-round: X[b][p] -> Xt[p][b] ----------
__global__ __launch_bounds__(256)
void transpose_in(const float* __restrict__ X, float* __restrict__ Xt)
{
    __shared__ float tt[64][65];
    const int tid = threadIdx.x;
    const int p0  = blockIdx.x * 64;

    #pragma unroll
    for (int i = 0; i < 4; i++) {
        const int u = tid + 256 * i;
        const int b = u >> 4;
        const int q = u & 15;
        float4 v = *(const float4*)(X + (size_t)b * P_TOT + p0 + 4 * q);
        tt[4 * q + 0][b] = v.x;
        tt[4 * q + 1][b] = v.y;
        tt[4 * q + 2][b] = v.z;
        tt[4 * q + 3][b] = v.w;
    }
    __syncthreads();
    #pragma unroll
    for (int i = 0; i < 4; i++) {
        const int u  = tid + 256 * i;
        const int p  = u >> 4;
        const int bq = u & 15;
        float4 o;
        o.x = __uint_as_float(f2tf(tt[p][4 * bq + 0]));
        o.y = __uint_as_float(f2tf(tt[p][4 * bq + 1]));
        o.z = __uint_as_float(f2tf(tt[p][4 * bq + 2]));
        o.w = __uint_as_float(f2tf(tt[p][4 * bq + 3]));
        *(float4*)(Xt + (size_t)(p0 + p) * BB + 4 * bq) = o;
    }
}

// ---------- output transpose: Os[s][bc] -> out[bc][s], 64x64 float4 tiles ----------
__global__ __launch_bounds__(256)
void transpose_out(const float* __restrict__ Os, float* __restrict__ out)
{
    __shared__ float tt[64][65];
    const int tid = threadIdx.x;
    const int bc0 = blockIdx.x * 64;
    const int s0  = blockIdx.y * 64;

    #pragma unroll
    for (int i = 0; i < 4; i++) {
        const int u  = tid + 256 * i;
        const int sl = u >> 4;
        const int q  = u & 15;
        float4 v = *(const float4*)(Os + (size_t)(s0 + sl) * (BB * CO) + bc0 + 4 * q);
        tt[4 * q + 0][sl] = v.x;
        tt[4 * q + 1][sl] = v.y;
        tt[4 * q + 2][sl] = v.z;
        tt[4 * q + 3][sl] = v.w;
    }
    __syncthreads();
    #pragma unroll
    for (int i = 0; i < 4; i++) {
        const int u  = tid + 256 * i;
        const int bl = u >> 4;
        const int sq = u & 15;
        float4 o;
        o.x = tt[bl][4 * sq + 0];
        o.y = tt[bl][4 * sq + 1];
        o.z = tt[bl][4 * sq + 2];
        o.w = tt[bl][4 * sq + 3];
        *(float4*)(out + (size_t)(bc0 + bl) * S_TOT + s0 + 4 * sq) = o;
    }
}

// ---------- main kernel ----------
__device__ __forceinline__ void cp16(unsigned dst, const void* src, bool ok)
{
    int sz = ok ? 16 : 0;
    asm volatile("cp.async.cg.shared.global [%0], [%1], 16, %2;\n"
                 :: "r"(dst), "l"(src), "r"(sz) : "memory");
}
#define CP_COMMIT() asm volatile("cp.async.commit_group;\n" ::: "memory")
#define CP_WAIT(N)  asm volatile("cp.async.wait_group %0;\n" :: "n"(N) : "memory")

__global__ __launch_bounds__(256)
void varconv_mma(const float* __restrict__ Wg,
                 const float* __restrict__ bias,
                 float* __restrict__ Os)
{
    extern __shared__ float smf[];
    const unsigned smb = (unsigned)__cvta_generic_to_shared(smf);

    const int s    = blockIdx.x;
    const int y    = s >> 6;
    const int x    = s & 63;
    const int tid  = threadIdx.x;
    const int lane = tid & 31;
    const int wid  = tid >> 5;
    const int mt   = wid & 3;        // m-tile (batch group of 16)
    const int kh   = wid >> 2;       // K-half: i-steps [0,5) / [5,9)

    const float* wp = Wg + (size_t)s * (KK * CO);

    // ---- stage W (288x16 fp32, row stride 24) via cp.async, 256 threads ----
    for (int i = tid; i < KK * 4; i += 256) {
        const int k = i >> 2;
        const int q = i & 3;
        cp16(smb + (unsigned)(k * WST + q * 4) * 4u, wp + k * CO + q * 4, true);
    }

    // ---- stage one X chunk (72 k-rows x 64 batches, tf32 bits) ----
    auto stage_x = [&](int chunk, int bufoff) {
        const int q = tid & 15;       // 16B unit in row
        for (int r = tid >> 4; r < CKR; r += 16) {
            const int k   = chunk * CKR + r;
            const int cl  = k / 9;
            const int tap = k - cl * 9;
            const int t3  = tap / 3;
            const int yy  = y + t3 - 1;
            const int xx  = x + (tap - 3 * t3) - 1;
            const bool ok = ((unsigned)yy < (unsigned)HH) & ((unsigned)xx < (unsigned)WW);
            const float* src = ok
                ? g_Xt + ((size_t)((cl << 12) + (yy << 6) + xx) << 6) + q * 4
                : g_Xt;
            cp16(smb + (unsigned)(bufoff + r * AST + q * 4) * 4u, src, ok);
        }
    };

    stage_x(0, XB0_OFF);
    CP_COMMIT();                          // G0 = W + X0
    stage_x(1, XB1_OFF);
    CP_COMMIT();                          // G1 = X1

    // fragment roles (batch permuted: m-row r -> batch mt*16 + 2*(r&7) + (r>>3))
    const int cc = lane & 3;
    const int r4 = lane >> 2;
    const int aoff = cc * AST + mt * 16 + 2 * r4;
    const int woff = cc * WST + r4;
    const int i0 = kh ? 5 : 0;
    const int i1 = kh ? 9 : 5;

    float acc[2][4] = {};
    float cs0 = 0.f, cs1 = 0.f;

    auto compute = [&](int bufoff, int chunk) {
        for (int i = i0; i < i1; i++) {
            const int ab = bufoff + i * (8 * AST) + aoff;
            const uint2 a01 = *(const uint2*)&smf[ab];
            const uint2 a23 = *(const uint2*)&smf[ab + 4 * AST];
            const int wb = (chunk * CKR + i * 8) * WST + woff;
            const float w0 = smf[wb];
            const float w1 = smf[wb + 4 * WST];
            const float w2 = smf[wb + 8];
            const float w3 = smf[wb + 4 * WST + 8];
            cs0 += w0 + w1;
            cs1 += w2 + w3;
            const unsigned b00 = f2tf(w0), b01 = f2tf(w1);
            const unsigned b10 = f2tf(w2), b11 = f2tf(w3);
            asm volatile(
                "mma.sync.aligned.m16n8k8.row.col.f32.tf32.tf32.f32 "
                "{%0,%1,%2,%3}, {%4,%5,%6,%7}, {%8,%9}, {%0,%1,%2,%3};"
                : "+f"(acc[0][0]), "+f"(acc[0][1]), "+f"(acc[0][2]), "+f"(acc[0][3])
                : "r"(a01.x), "r"(a01.y), "r"(a23.x), "r"(a23.y),
                  "r"(b00), "r"(b01));
            asm volatile(
                "mma.sync.aligned.m16n8k8.row.col.f32.tf32.tf32.f32 "
                "{%0,%1,%2,%3}, {%4,%5,%6,%7}, {%8,%9}, {%0,%1,%2,%3};"
                : "+f"(acc[1][0]), "+f"(acc[1][1]), "+f"(acc[1][2]), "+f"(acc[1][3])
                : "r"(a01.x), "r"(a01.y), "r"(a23.x), "r"(a23.y),
                  "r"(b10), "r"(b11));
        }
    };

    CP_WAIT(1); __syncthreads();          // W + chunk0 visible
    compute(XB0_OFF, 0);
    __syncthreads();
    stage_x(2, XB0_OFF); CP_COMMIT();

    CP_WAIT(1); __syncthreads();          // chunk1 visible
    compute(XB1_OFF, 1);
    __syncthreads();
    stage_x(3, XB1_OFF); CP_COMMIT();

    CP_WAIT(1); __syncthreads();          // chunk2 visible
    compute(XB0_OFF, 2);

    CP_WAIT(0); __syncthreads();          // chunk3 visible
    compute(XB1_OFF, 3);

    // ---- colsum partials: quad-reduce; mt==0 warp of each kh publishes ----
    cs0 += __shfl_xor_sync(0xffffffffu, cs0, 1);
    cs0 += __shfl_xor_sync(0xffffffffu, cs0, 2);
    cs1 += __shfl_xor_sync(0xffffffffu, cs1, 1);
    cs1 += __shfl_xor_sync(0xffffffffu, cs1, 2);
    if (mt == 0 && cc == 0) {
        smf[CSUM_OFF + kh * 16 + r4]     = cs0;   // c = r4
        smf[CSUM_OFF + kh * 16 + 8 + r4] = cs1;   // c = r4 + 8
    }

    // ---- kh=1 warps dump partial accs to pad ----
    if (kh == 1) {
        const int pb = PAD_OFF + ((mt * 32 + lane) << 3);
        *(float4*)&smf[pb]     = make_float4(acc[0][0], acc[0][1], acc[0][2], acc[0][3]);
        *(float4*)&smf[pb + 4] = make_float4(acc[1][0], acc[1][1], acc[1][2], acc[1][3]);
    }
    __syncthreads();

    // ---- kh=0 warps: combine halves + bias, STG.64 pairs into Os ----
    if (kh == 0) {
        const float bval = bias[s];
        float* os = Os + (size_t)s * (BB * CO);
        const int pb = PAD_OFF + ((mt * 32 + lane) << 3);
        const float4 p0 = *(const float4*)&smf[pb];
        const float4 p1 = *(const float4*)&smf[pb + 4];
        acc[0][0] += p0.x; acc[0][1] += p0.y; acc[0][2] += p0.z; acc[0][3] += p0.w;
        acc[1][0] += p1.x; acc[1][1] += p1.y; acc[1][2] += p1.z; acc[1][3] += p1.w;

        const int blo = mt * 16 + 2 * r4;         // rows r4 / r4+8 -> b, b+1
        #pragma unroll
        for (int nt = 0; nt < 2; nt++) {
            const int c = nt * 8 + 2 * cc;
            const float t0 = bval * (smf[CSUM_OFF + c]     + smf[CSUM_OFF + 16 + c]);
            const float t1 = bval * (smf[CSUM_OFF + c + 1] + smf[CSUM_OFF + 16 + c + 1]);
            float2 v0 = make_float2(acc[nt][0] + t0, acc[nt][1] + t1);
            float2 v1 = make_float2(acc[nt][2] + t0, acc[nt][3] + t1);
            *(float2*)&os[blo * CO + c]       = v0;
            *(float2*)&os[(blo + 1) * CO + c] = v1;
        }
    }
}

extern "C" void kernel_launch(void* const* d_in, const int* in_sizes, int n_in,
                              void* d_out, int out_size)
{
    const float* X    = (const float*)d_in[0];
    const float* Wg   = (const float*)d_in[1];
    const float* bias = (const float*)d_in[2];
    float* out        = (float*)d_out;
    (void)in_sizes; (void)n_in; (void)out_size;

    float *Xt = nullptr, *Os = nullptr;
    cudaGetSymbolAddress((void**)&Xt, g_Xt);
    cudaGetSymbolAddress((void**)&Os, g_Os);

    cudaFuncSetAttribute(varconv_mma,
                         cudaFuncAttributeMaxDynamicSharedMemorySize, SMEM_BYTES);

    transpose_in<<<P_TOT / 64, 256>>>(X, Xt);

    varconv_mma<<<S_TOT, 256, SMEM_BYTES>>>(Wg, bias, Os);

    transpose_out<<<dim3((BB * CO) / 64, S_TOT / 64), 256>>>(Os, out);
}

// round 14
// speedup vs baseline: 1.3143x; 1.3143x over previous
#include <cuda_runtime.h>
#include <cstddef>
#include <cstdint>

// VarConvND: 4096 independent GEMMs [B=64 x K=288] x [K=288 x C_OUT=16].
// tf32 MMA, 128 threads (4 warps = 4 batch m-tiles), K double-buffered
// (4 chunks x 72 rows), BOTH X and W staged per-chunk via cp.async.
//   out[b,c,s] = sum_k u[b,k]*w[k,c] + bias[s]*sum_k w[k,c]

#define S_TOT 4096
#define KK    288
#define CO    16
#define CI    32
#define BB    64
#define HH    64
#define WW    64
#define P_TOT (CI*HH*WW)            // 131072

#define AST   72                    // X row stride (words): A-frag reads hit 32 banks
#define WST   24                    // W row stride (words): B-frag reads hit 32 banks
#define CKR   72                    // k-rows per chunk
#define NCH   4                     // chunks

#define XB_WORDS (CKR*AST)          // 5184
#define WB_WORDS (CKR*WST)          // 1728
#define XB0_OFF  0
#define XB1_OFF  XB_WORDS
#define WB0_OFF  (2*XB_WORDS)
#define WB1_OFF  (2*XB_WORDS + WB_WORDS)
#define CSUM_OFF (2*XB_WORDS + 2*WB_WORDS)
#define SMEM_WORDS (CSUM_OFF + 16)
#define SMEM_BYTES (SMEM_WORDS * 4)   // 55,360 -> 4 CTAs/SM

__device__ float g_Xt[(size_t)P_TOT * BB];        // X^T, tf32-rounded, [p][b]
__device__ float g_Os[(size_t)S_TOT * BB * CO];   // out scratch [s][b*16+c]

__device__ __forceinline__ unsigned f2tf(float f)
{
    unsigned u;
    asm("cvt.rna.tf32.f32 %0, %1;" : "=r"(u) : "f"(f));
    return u;
}

// ---------- transpose + tf32-round: X[b][p] -> Xt[p][b] ----------
__global__ __launch_bounds__(256)
void transpose_in(const float* __restrict__ X, float* __restrict__ Xt)
{
    __shared__ float tt[64][65];
    const int tid = threadIdx.x;
    const int p0  = blockIdx.x * 64;

    #pragma unroll
    for (int i = 0; i < 4; i++) {
        const int u = tid + 256 * i;
        const int b = u >> 4;
        const int q = u & 15;
        float4 v = *(const float4*)(X + (size_t)b * P_TOT + p0 + 4 * q);
        tt[4 * q + 0][b] = v.x;
        tt[4 * q + 1][b] = v.y;
        tt[4 * q + 2][b] = v.z;
        tt[4 * q + 3][b] = v.w;
    }
    __syncthreads();
    #pragma unroll
    for (int i = 0; i < 4; i++) {
        const int u  = tid + 256 * i;
        const int p  = u >> 4;
        const int bq = u & 15;
        float4 o;
        o.x = __uint_as_float(f2tf(tt[p][4 * bq + 0]));
        o.y = __uint_as_float(f2tf(tt[p][4 * bq + 1]));
        o.z = __uint_as_float(f2tf(tt[p][4 * bq + 2]));
        o.w = __uint_as_float(f2tf(tt[p][4 * bq + 3]));
        *(float4*)(Xt + (size_t)(p0 + p) * BB + 4 * bq) = o;
    }
}

// ---------- output transpose: Os[s][bc] -> out[bc][s], 64x64 float4 tiles ----------
__global__ __launch_bounds__(256)
void transpose_out(const float* __restrict__ Os, float* __restrict__ out)
{
    __shared__ float tt[64][65];
    const int tid = threadIdx.x;
    const int bc0 = blockIdx.x * 64;
    const int s0  = blockIdx.y * 64;

    #pragma unroll
    for (int i = 0; i < 4; i++) {
        const int u  = tid + 256 * i;
        const int sl = u >> 4;
        const int q  = u & 15;
        float4 v = *(const float4*)(Os + (size_t)(s0 + sl) * (BB * CO) + bc0 + 4 * q);
        tt[4 * q + 0][sl] = v.x;
        tt[4 * q + 1][sl] = v.y;
        tt[4 * q + 2][sl] = v.z;
        tt[4 * q + 3][sl] = v.w;
    }
    __syncthreads();
    #pragma unroll
    for (int i = 0; i < 4; i++) {
        const int u  = tid + 256 * i;
        const int bl = u >> 4;
        const int sq = u & 15;
        float4 o;
        o.x = tt[bl][4 * sq + 0];
        o.y = tt[bl][4 * sq + 1];
        o.z = tt[bl][4 * sq + 2];
        o.w = tt[bl][4 * sq + 3];
        *(float4*)(out + (size_t)(bc0 + bl) * S_TOT + s0 + 4 * sq) = o;
    }
}

// ---------- main kernel ----------
__device__ __forceinline__ void cp16(unsigned dst, const void* src, bool ok)
{
    int sz = ok ? 16 : 0;
    asm volatile("cp.async.cg.shared.global [%0], [%1], 16, %2;\n"
                 :: "r"(dst), "l"(src), "r"(sz) : "memory");
}
#define CP_COMMIT() asm volatile("cp.async.commit_group;\n" ::: "memory")
#define CP_WAIT(N)  asm volatile("cp.async.wait_group %0;\n" :: "n"(N) : "memory")

__global__ __launch_bounds__(128)
void varconv_mma(const float* __restrict__ Wg,
                 const float* __restrict__ bias,
                 float* __restrict__ Os)
{
    extern __shared__ float smf[];
    const unsigned smb = (unsigned)__cvta_generic_to_shared(smf);

    const int s    = blockIdx.x;
    const int y    = s >> 6;
    const int x    = s & 63;
    const int tid  = threadIdx.x;
    const int lane = tid & 31;
    const int wid  = tid >> 5;

    const float* wp = Wg + (size_t)s * (KK * CO);

    // ---- stage one W chunk (72 rows x 16, row stride 24) ----
    auto stage_w = [&](int chunk, int bufoff) {
        const int q  = tid & 3;           // 16B unit (4 c's)
        const int r0 = tid >> 2;          // 0..31
        #pragma unroll
        for (int i = 0; i < 2; i++) {     // rows r0, r0+32
            const int r = r0 + 32 * i;
            cp16(smb + (unsigned)(bufoff + r * WST + q * 4) * 4u,
                 wp + (chunk * CKR + r) * CO + q * 4, true);
        }
        if (r0 < 8) {                     // rows 64..71
            const int r = 64 + r0;
            cp16(smb + (unsigned)(bufoff + r * WST + q * 4) * 4u,
                 wp + (chunk * CKR + r) * CO + q * 4, true);
        }
    };

    // ---- stage one X chunk (72 k-rows x 64 batches, tf32 bits) ----
    auto stage_x = [&](int chunk, int bufoff) {
        const int r0 = tid >> 4;          // 0..7
        const int q  = tid & 15;          // 16B unit in row
        #pragma unroll
        for (int i = 0; i < 9; i++) {
            const int r   = r0 + 8 * i;   // 0..71
            const int k   = chunk * CKR + r;
            const int cl  = k / 9;
            const int tap = k - cl * 9;
            const int t3  = tap / 3;
            const int yy  = y + t3 - 1;
            const int xx  = x + (tap - 3 * t3) - 1;
            const bool ok = ((unsigned)yy < (unsigned)HH) & ((unsigned)xx < (unsigned)WW);
            const float* src = ok
                ? g_Xt + ((size_t)((cl << 12) + (yy << 6) + xx) << 6) + q * 4
                : g_Xt;
            cp16(smb + (unsigned)(bufoff + r * AST + q * 4) * 4u, src, ok);
        }
    };

    stage_w(0, WB0_OFF);
    stage_x(0, XB0_OFF);
    CP_COMMIT();                          // G0 = W0 + X0
    stage_w(1, WB1_OFF);
    stage_x(1, XB1_OFF);
    CP_COMMIT();                          // G1 = W1 + X1

    // fragment roles (batch permuted: m-row r -> batch wid*16 + 2*(r&7) + (r>>3))
    const int cc = lane & 3;
    const int r4 = lane >> 2;
    const int aoff = cc * AST + wid * 16 + 2 * r4;   // rows (r4, r4+8) adjacent
    const int woff = cc * WST + r4;

    float acc[2][4] = {};
    float cs0 = 0.f, cs1 = 0.f;

    auto compute = [&](int xbuf, int wbuf) {
        #pragma unroll
        for (int i = 0; i < 9; i++) {
            const int ab = xbuf + i * (8 * AST) + aoff;
            const uint2 a01 = *(const uint2*)&smf[ab];
            const uint2 a23 = *(const uint2*)&smf[ab + 4 * AST];
            const int wb = wbuf + i * (8 * WST) + woff;
            const float w0 = smf[wb];
            const float w1 = smf[wb + 4 * WST];
            const float w2 = smf[wb + 8];
            const float w3 = smf[wb + 4 * WST + 8];
            cs0 += w0 + w1;
            cs1 += w2 + w3;
            const unsigned b00 = f2tf(w0), b01 = f2tf(w1);
            const unsigned b10 = f2tf(w2), b11 = f2tf(w3);
            asm volatile(
                "mma.sync.aligned.m16n8k8.row.col.f32.tf32.tf32.f32 "
                "{%0,%1,%2,%3}, {%4,%5,%6,%7}, {%8,%9}, {%0,%1,%2,%3};"
                : "+f"(acc[0][0]), "+f"(acc[0][1]), "+f"(acc[0][2]), "+f"(acc[0][3])
                : "r"(a01.x), "r"(a01.y), "r"(a23.x), "r"(a23.y),
                  "r"(b00), "r"(b01));
            asm volatile(
                "mma.sync.aligned.m16n8k8.row.col.f32.tf32.tf32.f32 "
                "{%0,%1,%2,%3}, {%4,%5,%6,%7}, {%8,%9}, {%0,%1,%2,%3};"
                : "+f"(acc[1][0]), "+f"(acc[1][1]), "+f"(acc[1][2]), "+f"(acc[1][3])
                : "r"(a01.x), "r"(a01.y), "r"(a23.x), "r"(a23.y),
                  "r"(b10), "r"(b11));
        }
    };

    CP_WAIT(1); __syncthreads();          // W0 + X0 visible
    compute(XB0_OFF, WB0_OFF);
    __syncthreads();
    stage_w(2, WB0_OFF); stage_x(2, XB0_OFF); CP_COMMIT();

    CP_WAIT(1); __syncthreads();          // W1 + X1 visible
    compute(XB1_OFF, WB1_OFF);
    __syncthreads();
    stage_w(3, WB1_OFF); stage_x(3, XB1_OFF); CP_COMMIT();

    CP_WAIT(1); __syncthreads();          // chunk2 visible
    compute(XB0_OFF, WB0_OFF);

    CP_WAIT(0); __syncthreads();          // chunk3 visible
    compute(XB1_OFF, WB1_OFF);

    // ---- colsum: quad-reduce; warp 0 publishes ----
    cs0 += __shfl_xor_sync(0xffffffffu, cs0, 1);
    cs0 += __shfl_xor_sync(0xffffffffu, cs0, 2);
    cs1 += __shfl_xor_sync(0xffffffffu, cs1, 1);
    cs1 += __shfl_xor_sync(0xffffffffu, cs1, 2);
    if (wid == 0 && cc == 0) {
        smf[CSUM_OFF + r4]     = cs0;   // c = r4
        smf[CSUM_OFF + 8 + r4] = cs1;   // c = r4 + 8
    }
    __syncthreads();

    // ---- epilogue: STG.64 pairs into Os[s][b*16+c] ----
    {
        const float bval = bias[s];
        float* os = Os + (size_t)s * (BB * CO);
        const int blo = wid * 16 + 2 * r4;        // rows r4 / r4+8 -> b, b+1
        #pragma unroll
        for (int nt = 0; nt < 2; nt++) {
            const int c = nt * 8 + 2 * cc;
            const float t0 = bval * smf[CSUM_OFF + c];
            const float t1 = bval * smf[CSUM_OFF + c + 1];
            float2 v0 = make_float2(acc[nt][0] + t0, acc[nt][1] + t1);
            float2 v1 = make_float2(acc[nt][2] + t0, acc[nt][3] + t1);
            *(float2*)&os[blo * CO + c]       = v0;
            *(float2*)&os[(blo + 1) * CO + c] = v1;
        }
    }
}

extern "C" void kernel_launch(void* const* d_in, const int* in_sizes, int n_in,
                              void* d_out, int out_size)
{
    const float* X    = (const float*)d_in[0];
    const float* Wg   = (const float*)d_in[1];
    const float* bias = (const float*)d_in[2];
    float* out        = (float*)d_out;
    (void)in_sizes; (void)n_in; (void)out_size;

    float *Xt = nullptr, *Os = nullptr;
    cudaGetSymbolAddress((void**)&Xt, g_Xt);
    cudaGetSymbolAddress((void**)&Os, g_Os);

    cudaFuncSetAttribute(varconv_mma,
                         cudaFuncAttributeMaxDynamicSharedMemorySize, SMEM_BYTES);

    transpose_in<<<P_TOT / 64, 256>>>(X, Xt);

    varconv_mma<<<S_TOT, 128, SMEM_BYTES>>>(Wg, bias, Os);

    transpose_out<<<dim3((BB * CO) / 64, S_TOT / 64), 256>>>(Os, out);
}

// round 16
// speedup vs baseline: 1.6328x; 1.2424x over previous
#include <cuda_runtime.h>
#include <cuda_fp16.h>
#include <cstddef>
#include <cstdint>

// VarConvND: 4096 independent GEMMs [B=64 x K=288] x [K=288 x C_OUT=16].
// fp16 MMA m16n8k16 (fp32 accum): m = C_OUT, n = batch.
// K pipelined: 3 chunks x 96 rows, double-buffered via cp.async.
//   out[b,c,s] = sum_k u[b,k]*w[k,c] + bias[s]*sum_k w[k,c]

#define S_TOT 4096
#define KK    288
#define CO    16
#define CI    32
#define BB    64
#define HH    64
#define WW    64
#define P_TOT (CI*HH*WW)            // 131072

#define CKR   96                    // k-rows per chunk (6 k16 steps)
#define HST   72                    // X smem row stride in halfs (144 B)
#define WSTW  20                    // W smem row stride in words

#define XB_HALFS (CKR*HST)          // 6912 halfs = 3456 words
#define WB_WORDS (CKR*WSTW)         // 1920 words
#define XB0H  0
#define XB1H  XB_HALFS
#define WB0   (XB_HALFS)            // word offset (2*XB_HALFS halfs = XB_HALFS words)
#define WB1   (XB_HALFS + WB_WORDS)
#define SMEM_WORDS (XB_HALFS + 2*WB_WORDS)
#define SMEM_BYTES (SMEM_WORDS * 4)          // 43,008 B -> 5 CTAs/SM

__device__ __half g_Xt[(size_t)P_TOT * BB];       // X^T fp16, [p][b]
__device__ float  g_Os[(size_t)S_TOT * BB * CO];  // out scratch [s][c*64+b]

__device__ __forceinline__ unsigned h2_bits(__half2 h)
{
    return *reinterpret_cast<unsigned*>(&h);
}

// ---------- transpose + fp16-round: X[b][p] fp32 -> Xt[p][b] fp16 ----------
__global__ __launch_bounds__(256)
void transpose_in(const float* __restrict__ X, __half* __restrict__ Xt)
{
    __shared__ float tt[64][65];
    const int tid = threadIdx.x;
    const int p0  = blockIdx.x * 64;

    #pragma unroll
    for (int i = 0; i < 4; i++) {
        const int u = tid + 256 * i;
        const int b = u >> 4;
        const int q = u & 15;
        float4 v = *(const float4*)(X + (size_t)b * P_TOT + p0 + 4 * q);
        tt[4 * q + 0][b] = v.x;
        tt[4 * q + 1][b] = v.y;
        tt[4 * q + 2][b] = v.z;
        tt[4 * q + 3][b] = v.w;
    }
    __syncthreads();
    #pragma unroll
    for (int i = 0; i < 2; i++) {
        const int u = tid + 256 * i;      // 512 units: 64 rows x 8 units of 8 halfs
        const int p = u >> 3;
        const int q = u & 7;
        uint4 o;
        o.x = h2_bits(__floats2half2_rn(tt[p][8 * q + 0], tt[p][8 * q + 1]));
        o.y = h2_bits(__floats2half2_rn(tt[p][8 * q + 2], tt[p][8 * q + 3]));
        o.z = h2_bits(__floats2half2_rn(tt[p][8 * q + 4], tt[p][8 * q + 5]));
        o.w = h2_bits(__floats2half2_rn(tt[p][8 * q + 6], tt[p][8 * q + 7]));
        *(uint4*)(Xt + (size_t)(p0 + p) * BB + 8 * q) = o;
    }
}

// ---------- output transpose: Os[s][c*64+b] -> out[(b*16+c)][s] ----------
__global__ __launch_bounds__(256)
void transpose_out(const float* __restrict__ Os, float* __restrict__ out)
{
    __shared__ float tt[64][65];
    const int tid = threadIdx.x;
    const int j0  = blockIdx.x * 64;     // Os col block: c = j0>>6, b = 0..63
    const int s0  = blockIdx.y * 64;
    const int cX  = j0 >> 6;

    #pragma unroll
    for (int i = 0; i < 4; i++) {
        const int u  = tid + 256 * i;
        const int sl = u >> 4;
        const int q  = u & 15;
        float4 v = *(const float4*)(Os + (size_t)(s0 + sl) * (BB * CO) + j0 + 4 * q);
        tt[4 * q + 0][sl] = v.x;
        tt[4 * q + 1][sl] = v.y;
        tt[4 * q + 2][sl] = v.z;
        tt[4 * q + 3][sl] = v.w;
    }
    __syncthreads();
    #pragma unroll
    for (int i = 0; i < 4; i++) {
        const int u  = tid + 256 * i;
        const int bl = u >> 4;           // b
        const int sq = u & 15;
        float4 o;
        o.x = tt[bl][4 * sq + 0];
        o.y = tt[bl][4 * sq + 1];
        o.z = tt[bl][4 * sq + 2];
        o.w = tt[bl][4 * sq + 3];
        *(float4*)(out + (size_t)(bl * CO + cX) * S_TOT + s0 + 4 * sq) = o;
    }
}

// ---------- main kernel ----------
__device__ __forceinline__ void cp16(unsigned dst, const void* src, bool ok)
{
    int sz = ok ? 16 : 0;
    asm volatile("cp.async.cg.shared.global [%0], [%1], 16, %2;\n"
                 :: "r"(dst), "l"(src), "r"(sz) : "memory");
}
#define CP_COMMIT() asm volatile("cp.async.commit_group;\n" ::: "memory")
#define CP_WAIT(N)  asm volatile("cp.async.wait_group %0;\n" :: "n"(N) : "memory")

__global__ __launch_bounds__(128)
void varconv_mma(const float* __restrict__ Wg,
                 const float* __restrict__ bias,
                 float* __restrict__ Os)
{
    extern __shared__ float smf[];
    const unsigned smb = (unsigned)__cvta_generic_to_shared(smf);

    const int s    = blockIdx.x;
    const int y    = s >> 6;
    const int x    = s & 63;
    const int tid  = threadIdx.x;
    const int lane = tid & 31;
    const int wid  = tid >> 5;       // warp -> n-block of 16 batches

    const float* wp = Wg + (size_t)s * (KK * CO);

    // ---- stage one W chunk (96 rows x 16 fp32, stride 20 words) ----
    auto stage_w = [&](int chunk, int wbuf) {
        const int q  = tid & 3;           // 16B unit (4 c's)
        const int r0 = tid >> 2;          // 0..31
        #pragma unroll
        for (int j = 0; j < 3; j++) {     // rows r0, r0+32, r0+64
            const int r = r0 + 32 * j;
            cp16(smb + (unsigned)(wbuf + r * WSTW + q * 4) * 4u,
                 wp + (chunk * CKR + r) * CO + q * 4, true);
        }
    };

    // ---- stage one X chunk (96 k-rows x 64 batches fp16, stride 72 halfs) ----
    auto stage_x = [&](int chunk, int xbufh) {
        const int q  = tid & 7;           // 16B unit (8 halfs)
        const int r0 = tid >> 3;          // 0..15
        #pragma unroll
        for (int j = 0; j < 6; j++) {
            const int r   = r0 + 16 * j;  // 0..95
            const int k   = chunk * CKR + r;
            const int cl  = k / 9;
            const int tap = k - cl * 9;
            const int t3  = tap / 3;
            const int yy  = y + t3 - 1;
            const int xx  = x + (tap - 3 * t3) - 1;
            const bool ok = ((unsigned)yy < (unsigned)HH) & ((unsigned)xx < (unsigned)WW);
            const __half* src = ok
                ? g_Xt + ((size_t)((cl << 12) + (yy << 6) + xx) << 6) + q * 8
                : g_Xt;
            cp16(smb + (unsigned)(xbufh + r * HST + q * 8) * 2u, src, ok);
        }
    };

    stage_w(0, WB0);
    stage_x(0, XB0H);
    CP_COMMIT();                          // G0 = W0 + X0
    stage_w(1, WB1);
    stage_x(1, XB1H);
    CP_COMMIT();                          // G1 = W1 + X1

    // fragment roles
    const int cc = lane & 3;
    const int r4 = lane >> 2;
    // ldmatrix B address components (X smem, halfs)
    const int ln_k = (lane & 7) + 8 * ((lane >> 3) & 1);
    const int ln_n = wid * 16 + 8 * (lane >> 4);

    float acc[2][4] = {};
    float cs0 = 0.f, cs1 = 0.f;

    auto compute = [&](int xbufh, int wbuf) {
        #pragma unroll
        for (int i = 0; i < 6; i++) {
            // ---- A from fp32 W smem: 8 LDS.32 + 4 cvt-pack ----
            const int wr = wbuf + (16 * i + 2 * cc) * WSTW;
            const float wa  = smf[wr + r4];
            const float wb_ = smf[wr + WSTW + r4];
            const float wc  = smf[wr + 8 * WSTW + r4];
            const float wd  = smf[wr + 9 * WSTW + r4];
            const float we  = smf[wr + r4 + 8];
            const float wf_ = smf[wr + WSTW + r4 + 8];
            const float wg  = smf[wr + 8 * WSTW + r4 + 8];
            const float wh  = smf[wr + 9 * WSTW + r4 + 8];
            cs0 += (wa + wb_) + (wc + wd);
            cs1 += (we + wf_) + (wg + wh);
            const unsigned a0 = h2_bits(__floats2half2_rn(wa, wb_));
            const unsigned a1 = h2_bits(__floats2half2_rn(we, wf_));
            const unsigned a2 = h2_bits(__floats2half2_rn(wc, wd));
            const unsigned a3 = h2_bits(__floats2half2_rn(wg, wh));

            // ---- B from fp16 X smem via ldmatrix.x4.trans ----
            unsigned b0, b1, b2, b3;
            const unsigned baddr = smb +
                (unsigned)(xbufh + (16 * i + ln_k) * HST + ln_n) * 2u;
            asm volatile(
                "ldmatrix.sync.aligned.m8n8.x4.trans.shared.b16 "
                "{%0,%1,%2,%3}, [%4];"
                : "=r"(b0), "=r"(b1), "=r"(b2), "=r"(b3) : "r"(baddr));

            asm volatile(
                "mma.sync.aligned.m16n8k16.row.col.f32.f16.f16.f32 "
                "{%0,%1,%2,%3}, {%4,%5,%6,%7}, {%8,%9}, {%0,%1,%2,%3};"
                : "+f"(acc[0][0]), "+f"(acc[0][1]), "+f"(acc[0][2]), "+f"(acc[0][3])
                : "r"(a0), "r"(a1), "r"(a2), "r"(a3), "r"(b0), "r"(b1));
            asm volatile(
                "mma.sync.aligned.m16n8k16.row.col.f32.f16.f16.f32 "
                "{%0,%1,%2,%3}, {%4,%5,%6,%7}, {%8,%9}, {%0,%1,%2,%3};"
                : "+f"(acc[1][0]), "+f"(acc[1][1]), "+f"(acc[1][2]), "+f"(acc[1][3])
                : "r"(a0), "r"(a1), "r"(a2), "r"(a3), "r"(b2), "r"(b3));
        }
    };

    CP_WAIT(1); __syncthreads();          // W0 + X0 visible
    compute(XB0H, WB0);
    __syncthreads();                      // buffer-0 readers done
    stage_w(2, WB0); stage_x(2, XB0H); CP_COMMIT();

    CP_WAIT(1); __syncthreads();          // chunk1 visible
    compute(XB1H, WB1);

    CP_WAIT(0); __syncthreads();          // chunk2 visible
    compute(XB0H, WB0);

    // ---- colsum: each warp saw all k x c; reduce over cc lanes ----
    cs0 += __shfl_xor_sync(0xffffffffu, cs0, 1);
    cs0 += __shfl_xor_sync(0xffffffffu, cs0, 2);
    cs1 += __shfl_xor_sync(0xffffffffu, cs1, 1);
    cs1 += __shfl_xor_sync(0xffffffffu, cs1, 2);

    // ---- epilogue: D frag -> Os[s][c*64 + b], STG.64 pairs ----
    {
        const float bval = bias[s];
        const float bt0 = bval * cs0;     // c = r4
        const float bt1 = bval * cs1;     // c = r4 + 8
        float* os = Os + (size_t)s * (BB * CO);
        #pragma unroll
        for (int nt = 0; nt < 2; nt++) {
            const int nb = wid * 16 + 8 * nt + 2 * cc;   // batch pair
            *(float2*)&os[r4 * 64 + nb] =
                make_float2(acc[nt][0] + bt0, acc[nt][1] + bt0);
            *(float2*)&os[(r4 + 8) * 64 + nb] =
                make_float2(acc[nt][2] + bt1, acc[nt][3] + bt1);
        }
    }
}

extern "C" void kernel_launch(void* const* d_in, const int* in_sizes, int n_in,
                              void* d_out, int out_size)
{
    const float* X    = (const float*)d_in[0];
    const float* Wg   = (const float*)d_in[1];
    const float* bias = (const float*)d_in[2];
    float* out        = (float*)d_out;
    (void)in_sizes; (void)n_in; (void)out_size;

    __half* Xt = nullptr;
    float*  Os = nullptr;
    cudaGetSymbolAddress((void**)&Xt, g_Xt);
    cudaGetSymbolAddress((void**)&Os, g_Os);

    cudaFuncSetAttribute(varconv_mma,
                         cudaFuncAttributeMaxDynamicSharedMemorySize, SMEM_BYTES);

    transpose_in<<<P_TOT / 64, 256>>>(X, Xt);

    varconv_mma<<<S_TOT, 128, SMEM_BYTES>>>(Wg, bias, Os);

    transpose_out<<<dim3((BB * CO) / 64, S_TOT / 64), 256>>>(Os, out);
}